// round 4
// baseline (speedup 1.0000x reference)
#include <cuda_runtime.h>
#include <cstdint>
#include <cstddef>

#define HH   32
#define SQ   2048
#define SKK  2048
#define DHH  128
#define BM   128
#define BN   64
#define NTILES (SKK / BN)          // 32
#define VSTR 132                   // floats per V row in smem (128 + 4 pad, 528B = 33*16)
#define LOG2E 1.4426950408889634f

// two V buffers of [BN][VSTR] floats
#define SMEM_BYTES (2 * BN * VSTR * 4)

__device__ __forceinline__ uint32_t f2tf32(float f) {
    uint32_t u;
    asm("cvt.rna.tf32.f32 %0, %1;" : "=r"(u) : "f"(f));
    return u;
}
__device__ __forceinline__ float ex2f(float x) {
    float y;
    asm("ex2.approx.ftz.f32 %0, %1;" : "=f"(y) : "f"(x));
    return y;
}
__device__ __forceinline__ void cp16(uint32_t dst, const float* src) {
    asm volatile("cp.async.cg.shared.global [%0], [%1], 16;\n" :: "r"(dst), "l"(src));
}

__global__ __launch_bounds__(256, 2)
void attn_sink_kernel(const float* __restrict__ logits,
                      const float* __restrict__ value,
                      const float* __restrict__ sinks,
                      float* __restrict__ out)
{
    extern __shared__ float smem[];   // [2][BN][VSTR]

    const int qt   = blockIdx.x;      // 0..15
    const int h    = blockIdx.y;      // 0..31
    const int tid  = threadIdx.x;
    const int lane = tid & 31;
    const int wid  = tid >> 5;        // 0..7
    const int mg   = wid >> 1;        // M-group: rows [mg*32, mg*32+32)
    const int ng   = wid & 1;         // N-group: cols [ng*64, ng*64+64)
    const int lc   = lane & 3;
    const int lr   = lane >> 2;
    const int nb   = ng * 64;

    const float* Lg = logits + ((size_t)h * SQ + (size_t)qt * BM) * SKK;
    const float* Vg = value  + (size_t)h * SKK * DHH;

    const uint32_t sbase = (uint32_t)__cvta_generic_to_shared(smem);

    // ---- V staging: thread covers rows {wid + 8i}, float4 col = lane ----
    const int vr = wid;               // base row
    const int vc = lane;              // float4 column 0..31
    const float* vsrc = Vg + (size_t)vr * DHH + vc * 4;

    // prologue: stage tile 0 into buffer 0
    {
#pragma unroll
        for (int i = 0; i < 8; ++i) {
            int r = vr + 8 * i;
            cp16(sbase + (uint32_t)(r * VSTR + vc * 4) * 4u, vsrc + (size_t)(8 * i) * DHH);
        }
        asm volatile("cp.async.commit_group;\n");
    }

    // accumulators: [mi][nt][4]  (mi: 16-row subtiles; nt: 8 n-subtiles of this warp's half)
    float acc[2][8][4];
#pragma unroll
    for (int mi = 0; mi < 2; ++mi)
#pragma unroll
        for (int nt = 0; nt < 8; ++nt) {
            acc[mi][nt][0] = 0.f; acc[mi][nt][1] = 0.f;
            acc[mi][nt][2] = 0.f; acc[mi][nt][3] = 0.f;
        }
    float psum[2][2] = {{0.f, 0.f}, {0.f, 0.f}};

    for (int kt = 0; kt < NTILES; ++kt) {
        const int cur = kt & 1;

        __syncthreads();   // reads of buf[cur^1] from prev iter done before refill

        if (kt + 1 < NTILES) {
            const float* vs = vsrc + (size_t)(kt + 1) * BN * DHH;
            uint32_t db = sbase + (uint32_t)((cur ^ 1) * BN * VSTR) * 4u;
#pragma unroll
            for (int i = 0; i < 8; ++i) {
                int r = vr + 8 * i;
                cp16(db + (uint32_t)(r * VSTR + vc * 4) * 4u, vs + (size_t)(8 * i) * DHH);
            }
            asm volatile("cp.async.commit_group;\n");
            asm volatile("cp.async.wait_group 1;\n");   // tile kt's copy complete
        } else {
            asm volatile("cp.async.wait_group 0;\n");
        }
        __syncthreads();   // buf[cur] visible to all warps

        const float* Vs = smem + cur * BN * VSTR;
        const float* Lt = Lg + kt * BN;

#pragma unroll
        for (int half = 0; half < 2; ++half) {
            // ---- A fragments straight from GMEM (k-col permutation: mma col c <-> mem col 2c) ----
            float2 A[2][4][2];
#pragma unroll
            for (int mi = 0; mi < 2; ++mi) {
                const int r0 = mg * 32 + mi * 16 + lr;
#pragma unroll
                for (int kk = 0; kk < 4; ++kk) {
                    const int col = (half * 4 + kk) * 8 + 2 * lc;
                    A[mi][kk][0] = *(const float2*)(Lt + (size_t)r0 * SKK + col);
                    A[mi][kk][1] = *(const float2*)(Lt + (size_t)(r0 + 8) * SKK + col);
                }
            }
            // ---- exp -> tf32 probs + partial row sums ----
            uint32_t P[2][4][4];
#pragma unroll
            for (int mi = 0; mi < 2; ++mi)
#pragma unroll
                for (int kk = 0; kk < 4; ++kk) {
                    float p0 = ex2f(A[mi][kk][0].x * LOG2E);
                    float p2 = ex2f(A[mi][kk][0].y * LOG2E);
                    float p1 = ex2f(A[mi][kk][1].x * LOG2E);
                    float p3 = ex2f(A[mi][kk][1].y * LOG2E);
                    psum[mi][0] += p0 + p2;
                    psum[mi][1] += p1 + p3;
                    P[mi][kk][0] = f2tf32(p0);
                    P[mi][kk][1] = f2tf32(p1);
                    P[mi][kk][2] = f2tf32(p2);
                    P[mi][kk][3] = f2tf32(p3);
                }
            // ---- P @ V ----
#pragma unroll
            for (int kk = 0; kk < 4; ++kk) {
                const int k = half * 4 + kk;
                const float* vrow = Vs + (k * 8 + 2 * lc) * VSTR + nb;  // mem row 2c, this warp's n-half
#pragma unroll
                for (int nt = 0; nt < 8; ++nt) {
                    uint32_t b0 = __float_as_uint(vrow[nt * 8 + lr]);          // row 2c
                    uint32_t b1 = __float_as_uint(vrow[VSTR + nt * 8 + lr]);   // row 2c+1
#pragma unroll
                    for (int mi = 0; mi < 2; ++mi) {
                        asm volatile(
                            "mma.sync.aligned.m16n8k8.row.col.f32.tf32.tf32.f32 "
                            "{%0,%1,%2,%3}, {%4,%5,%6,%7}, {%8,%9}, {%0,%1,%2,%3};\n"
                            : "+f"(acc[mi][nt][0]), "+f"(acc[mi][nt][1]),
                              "+f"(acc[mi][nt][2]), "+f"(acc[mi][nt][3])
                            : "r"(P[mi][kk][0]), "r"(P[mi][kk][1]),
                              "r"(P[mi][kk][2]), "r"(P[mi][kk][3]),
                              "r"(b0), "r"(b1));
                    }
                }
            }
        }
    }

    // ---- reduce row sums over the quad (lane bits 0,1 = lc), add sink, normalize ----
#pragma unroll
    for (int mi = 0; mi < 2; ++mi)
#pragma unroll
        for (int j = 0; j < 2; ++j) {
            psum[mi][j] += __shfl_xor_sync(0xffffffffu, psum[mi][j], 1);
            psum[mi][j] += __shfl_xor_sync(0xffffffffu, psum[mi][j], 2);
        }
    const float snk = ex2f(sinks[h] * LOG2E);
    float inv[2][2];
#pragma unroll
    for (int mi = 0; mi < 2; ++mi) {
        inv[mi][0] = 1.0f / (psum[mi][0] + snk);
        inv[mi][1] = 1.0f / (psum[mi][1] + snk);
    }

    float* Ob = out + ((size_t)h * SQ + (size_t)qt * BM) * DHH;
#pragma unroll
    for (int mi = 0; mi < 2; ++mi) {
        const int r0 = mg * 32 + mi * 16 + lr;
        float* O0 = Ob + (size_t)r0 * DHH + nb + 2 * lc;
        float* O1 = Ob + (size_t)(r0 + 8) * DHH + nb + 2 * lc;
#pragma unroll
        for (int nt = 0; nt < 8; ++nt) {
            *(float2*)(O0 + nt * 8) =
                make_float2(acc[mi][nt][0] * inv[mi][0], acc[mi][nt][1] * inv[mi][0]);
            *(float2*)(O1 + nt * 8) =
                make_float2(acc[mi][nt][2] * inv[mi][1], acc[mi][nt][3] * inv[mi][1]);
        }
    }
}

extern "C" void kernel_launch(void* const* d_in, const int* in_sizes, int n_in,
                              void* d_out, int out_size)
{
    const float* logits = (const float*)d_in[0];
    const float* value  = (const float*)d_in[1];
    const float* sinks  = (const float*)d_in[2];
    float* out = (float*)d_out;

    cudaFuncSetAttribute(attn_sink_kernel,
                         cudaFuncAttributeMaxDynamicSharedMemorySize, SMEM_BYTES);

    dim3 grid(SQ / BM, HH, 1);
    attn_sink_kernel<<<grid, 256, SMEM_BYTES>>>(logits, value, sinks, out);
}